// round 1
// baseline (speedup 1.0000x reference)
#include <cuda_runtime.h>
#include <math.h>

// Problem constants (fixed by the dataset)
#define Bn   8
#define Tn   4096
#define Dm   512          // d_model
#define Ff   2048         // d_ff
#define Ee   8            // experts
#define NTOK (Bn*Tn)      // 32768
#define NASG (NTOK*2)     // 65536 assignments (top_k = 2)

// Scratch (static __device__ — allocation-free per harness rules)
__device__ int   g_cnt[Ee];
__device__ int   g_off[Ee];
__device__ int   g_fill[Ee];
__device__ int   g_rows[NASG];                  // token row per assignment slot
__device__ float g_h[(size_t)NASG * Ff];        // 512 MB intermediate H

// ---------------------------------------------------------------------------
// Zero the 'out' region of d_out and reset routing counters (graph-replay safe)
// ---------------------------------------------------------------------------
__global__ void zero_and_reset(float4* __restrict__ out4, int n4) {
    int i = blockIdx.x * blockDim.x + threadIdx.x;
    int stride = gridDim.x * blockDim.x;
    float4 z = make_float4(0.f, 0.f, 0.f, 0.f);
    for (; i < n4; i += stride) out4[i] = z;
    if (blockIdx.x == 0 && threadIdx.x < Ee) {
        g_cnt[threadIdx.x]  = 0;
        g_fill[threadIdx.x] = 0;
    }
}

// ---------------------------------------------------------------------------
// Routing: expert ids + histogram
// ---------------------------------------------------------------------------
__global__ void route_kernel(const int* __restrict__ tok, float* __restrict__ eid) {
    int i = blockIdx.x * blockDim.x + threadIdx.x;
    if (i >= NTOK) return;
    int b    = i >> 12;                    // i / Tn
    int base = b * Tn + tok[i];
    int e0 = base % Ee;
    int e1 = (base + 1) % Ee;
    eid[2 * i]     = (float)e0;
    eid[2 * i + 1] = (float)e1;
    atomicAdd(&g_cnt[e0], 1);
    atomicAdd(&g_cnt[e1], 1);
}

// Prefix-sum offsets (8 entries; single thread) + write expert_counts
__global__ void offsets_kernel(float* __restrict__ ecnt) {
    if (threadIdx.x == 0 && blockIdx.x == 0) {
        int s = 0;
        for (int e = 0; e < Ee; e++) {
            g_off[e] = s;
            ecnt[e]  = (float)g_cnt[e];
            s += g_cnt[e];
        }
    }
}

// Fill per-expert gather lists
__global__ void fill_kernel(const int* __restrict__ tok) {
    int i = blockIdx.x * blockDim.x + threadIdx.x;
    if (i >= NTOK) return;
    int b    = i >> 12;
    int base = b * Tn + tok[i];
    int e0 = base % Ee;
    int e1 = (base + 1) % Ee;
    int p0 = atomicAdd(&g_fill[e0], 1);
    g_rows[g_off[e0] + p0] = i;
    int p1 = atomicAdd(&g_fill[e1], 1);
    g_rows[g_off[e1] + p1] = i;
}

// ---------------------------------------------------------------------------
// GEMM1: H[slot, 0:2048] = gelu( Xgather[slot, 0:512] @ W1[e] + b1[e] )
// 128x128 tile, BK=8, 256 threads, 8x8 micro-tile
// ---------------------------------------------------------------------------
__global__ __launch_bounds__(256) void gemm1_kernel(
    const float* __restrict__ x,
    const float* __restrict__ W1,
    const float* __restrict__ b1)
{
    int e   = blockIdx.z;
    int cnt = g_cnt[e];
    int m0  = blockIdx.y * 128;
    if (m0 >= cnt) return;
    int off = g_off[e];
    int n0  = blockIdx.x * 128;
    const float* Bm = W1 + (size_t)e * Dm * Ff;

    __shared__ float As[8][128];
    __shared__ float Bs[8][128];

    int t  = threadIdx.x;
    int ar = t >> 1;             // A tile row (0..127)
    int ac = (t & 1) * 4;        // A tile col group (0 or 4)
    int br = t >> 5;             // B tile row (0..7)
    int bc = (t & 31) * 4;       // B tile col group

    int gi    = m0 + ar;
    int valid = (gi < cnt);
    int rowidx = valid ? g_rows[off + gi] : 0;
    const float* arow = x + (size_t)rowidx * Dm;

    int tx = t & 15, ty = t >> 4;
    int mfrag = ty * 8, nfrag = tx * 8;

    float acc[8][8];
#pragma unroll
    for (int ii = 0; ii < 8; ii++)
#pragma unroll
        for (int jj = 0; jj < 8; jj++) acc[ii][jj] = 0.f;

    for (int k0 = 0; k0 < Dm; k0 += 8) {
        float4 av = valid ? *(const float4*)(arow + k0 + ac)
                          : make_float4(0.f, 0.f, 0.f, 0.f);
        float4 bv = *(const float4*)(Bm + (size_t)(k0 + br) * Ff + n0 + bc);
        __syncthreads();
        As[ac + 0][ar] = av.x;
        As[ac + 1][ar] = av.y;
        As[ac + 2][ar] = av.z;
        As[ac + 3][ar] = av.w;
        *(float4*)&Bs[br][bc] = bv;
        __syncthreads();
#pragma unroll
        for (int kk = 0; kk < 8; kk++) {
            float a[8], bb[8];
            *(float4*)&a[0]  = *(const float4*)&As[kk][mfrag];
            *(float4*)&a[4]  = *(const float4*)&As[kk][mfrag + 4];
            *(float4*)&bb[0] = *(const float4*)&Bs[kk][nfrag];
            *(float4*)&bb[4] = *(const float4*)&Bs[kk][nfrag + 4];
#pragma unroll
            for (int ii = 0; ii < 8; ii++)
#pragma unroll
                for (int jj = 0; jj < 8; jj++)
                    acc[ii][jj] = fmaf(a[ii], bb[jj], acc[ii][jj]);
        }
    }

    // epilogue: bias + exact gelu -> H
#pragma unroll
    for (int ii = 0; ii < 8; ii++) {
        int m = m0 + mfrag + ii;
        if (m < cnt) {
            float* hrow = g_h + (size_t)(off + m) * Ff + n0 + nfrag;
#pragma unroll
            for (int jj = 0; jj < 8; jj++) {
                float v = acc[ii][jj] + b1[e * Ff + n0 + nfrag + jj];
                hrow[jj] = 0.5f * v * (1.0f + erff(v * 0.70710678118654752f));
            }
        }
    }
}

// ---------------------------------------------------------------------------
// GEMM2: out[row] += 0.25 * ( H[slot, 0:2048] @ W2[e] + b2[e] )
// ---------------------------------------------------------------------------
__global__ __launch_bounds__(256) void gemm2_kernel(
    const float* __restrict__ W2,
    const float* __restrict__ b2,
    float* __restrict__ out)
{
    int e   = blockIdx.z;
    int cnt = g_cnt[e];
    int m0  = blockIdx.y * 128;
    if (m0 >= cnt) return;
    int off = g_off[e];
    int n0  = blockIdx.x * 128;
    const float* Bm = W2 + (size_t)e * Ff * Dm;

    __shared__ float As[8][128];
    __shared__ float Bs[8][128];

    int t  = threadIdx.x;
    int ar = t >> 1;
    int ac = (t & 1) * 4;
    int br = t >> 5;
    int bc = (t & 31) * 4;

    int gi    = m0 + ar;
    int valid = (gi < cnt);
    const float* arow = g_h + (size_t)(off + (valid ? gi : 0)) * Ff;

    int tx = t & 15, ty = t >> 4;
    int mfrag = ty * 8, nfrag = tx * 8;

    float acc[8][8];
#pragma unroll
    for (int ii = 0; ii < 8; ii++)
#pragma unroll
        for (int jj = 0; jj < 8; jj++) acc[ii][jj] = 0.f;

    for (int k0 = 0; k0 < Ff; k0 += 8) {
        float4 av = valid ? *(const float4*)(arow + k0 + ac)
                          : make_float4(0.f, 0.f, 0.f, 0.f);
        float4 bv = *(const float4*)(Bm + (size_t)(k0 + br) * Dm + n0 + bc);
        __syncthreads();
        As[ac + 0][ar] = av.x;
        As[ac + 1][ar] = av.y;
        As[ac + 2][ar] = av.z;
        As[ac + 3][ar] = av.w;
        *(float4*)&Bs[br][bc] = bv;
        __syncthreads();
#pragma unroll
        for (int kk = 0; kk < 8; kk++) {
            float a[8], bb[8];
            *(float4*)&a[0]  = *(const float4*)&As[kk][mfrag];
            *(float4*)&a[4]  = *(const float4*)&As[kk][mfrag + 4];
            *(float4*)&bb[0] = *(const float4*)&Bs[kk][nfrag];
            *(float4*)&bb[4] = *(const float4*)&Bs[kk][nfrag + 4];
#pragma unroll
            for (int ii = 0; ii < 8; ii++)
#pragma unroll
                for (int jj = 0; jj < 8; jj++)
                    acc[ii][jj] = fmaf(a[ii], bb[jj], acc[ii][jj]);
        }
    }

    // epilogue: scale + bias, scatter-add (2 commutative float adds/elem total)
#pragma unroll
    for (int ii = 0; ii < 8; ii++) {
        int m = m0 + mfrag + ii;
        if (m < cnt) {
            int r = g_rows[off + m];
            float* orow = out + (size_t)r * Dm + n0 + nfrag;
#pragma unroll
            for (int jj = 0; jj < 8; jj++) {
                float v = 0.25f * (acc[ii][jj] + b2[e * Dm + n0 + nfrag + jj]);
                atomicAdd(&orow[jj], v);
            }
        }
    }
}

// ---------------------------------------------------------------------------
// Launch: out | expert_ids(float) | expert_counts(float) packed into d_out
// ---------------------------------------------------------------------------
extern "C" void kernel_launch(void* const* d_in, const int* in_sizes, int n_in,
                              void* d_out, int out_size) {
    const float* x   = (const float*)d_in[0];
    const int*   tok = (const int*)d_in[1];
    const float* W1  = (const float*)d_in[2];
    const float* b1  = (const float*)d_in[3];
    const float* W2  = (const float*)d_in[4];
    const float* b2  = (const float*)d_in[5];

    float* out  = (float*)d_out;
    float* eid  = out + (size_t)NTOK * Dm;       // 16777216
    float* ecnt = eid + (size_t)NASG;            // + 65536

    int n4 = (NTOK * Dm) / 4;
    zero_and_reset<<<4096, 256>>>((float4*)out, n4);
    route_kernel<<<NTOK / 256, 256>>>(tok, eid);
    offsets_kernel<<<1, 32>>>(ecnt);
    fill_kernel<<<NTOK / 256, 256>>>(tok);

    dim3 g1(Ff / 128, 256, Ee);   // n-tiles, max m-tiles (early exit), experts
    gemm1_kernel<<<g1, 256>>>(x, W1, b1);
    dim3 g2(Dm / 128, 256, Ee);
    gemm2_kernel<<<g2, 256>>>(W2, b2, out);
}

// round 3
// speedup vs baseline: 3.1162x; 3.1162x over previous
#include <cuda_runtime.h>
#include <cstdint>
#include <math.h>

// ---------------------------------------------------------------------------
// Problem constants
// ---------------------------------------------------------------------------
#define Bn   8
#define Tn   4096
#define Dm   512
#define Ff   2048
#define Ee   8
#define NTOK (Bn*Tn)
#define NASG (NTOK*2)

// ---------------------------------------------------------------------------
// Scratch
// ---------------------------------------------------------------------------
__device__ int   g_cnt[Ee];
__device__ int   g_off[Ee];
__device__ int   g_fill[Ee];
__device__ int   g_rows[NASG];
__device__ float g_h[(size_t)NASG * Ff];   // 512 MB intermediate

// ---------------------------------------------------------------------------
// Helpers
// ---------------------------------------------------------------------------
__device__ __forceinline__ uint32_t smem_u32(const void* p) {
    uint32_t a;
    asm("{ .reg .u64 t; cvta.to.shared.u64 t, %1; cvt.u32.u64 %0, t; }" : "=r"(a) : "l"(p));
    return a;
}
__device__ __forceinline__ uint32_t f2tf32(float f) {
    uint32_t r;
    asm("cvt.rna.tf32.f32 %0, %1;" : "=r"(r) : "f"(f));
    return r;
}
__device__ __forceinline__ void mma_tf32(float* c, const uint32_t* a, const uint32_t* b) {
    asm volatile(
        "mma.sync.aligned.m16n8k8.row.col.f32.tf32.tf32.f32 "
        "{%0,%1,%2,%3},{%4,%5,%6,%7},{%8,%9},{%0,%1,%2,%3};"
        : "+f"(c[0]), "+f"(c[1]), "+f"(c[2]), "+f"(c[3])
        : "r"(a[0]), "r"(a[1]), "r"(a[2]), "r"(a[3]), "r"(b[0]), "r"(b[1]));
}
#define CP16(dst_u32, src_ptr) \
    asm volatile("cp.async.cg.shared.global [%0], [%1], 16;" :: "r"(dst_u32), "l"(src_ptr))
#define CP_COMMIT() asm volatile("cp.async.commit_group;" ::: "memory")
#define CP_WAIT(n)  asm volatile("cp.async.wait_group %0;" :: "n"(n) : "memory")

// ---------------------------------------------------------------------------
// Small kernels (routing / zero)
// ---------------------------------------------------------------------------
__global__ void zero_and_reset(float4* __restrict__ out4, int n4) {
    int i = blockIdx.x * blockDim.x + threadIdx.x;
    int stride = gridDim.x * blockDim.x;
    float4 z = make_float4(0.f, 0.f, 0.f, 0.f);
    for (; i < n4; i += stride) out4[i] = z;
    if (blockIdx.x == 0 && threadIdx.x < Ee) {
        g_cnt[threadIdx.x]  = 0;
        g_fill[threadIdx.x] = 0;
    }
}

__global__ void route_kernel(const int* __restrict__ tok, float* __restrict__ eid) {
    int i = blockIdx.x * blockDim.x + threadIdx.x;
    if (i >= NTOK) return;
    int b = i >> 12;
    int base = b * Tn + tok[i];
    int e0 = base % Ee, e1 = (base + 1) % Ee;
    eid[2 * i]     = (float)e0;
    eid[2 * i + 1] = (float)e1;
    atomicAdd(&g_cnt[e0], 1);
    atomicAdd(&g_cnt[e1], 1);
}

__global__ void offsets_kernel(float* __restrict__ ecnt) {
    if (threadIdx.x == 0 && blockIdx.x == 0) {
        int s = 0;
        for (int e = 0; e < Ee; e++) { g_off[e] = s; ecnt[e] = (float)g_cnt[e]; s += g_cnt[e]; }
    }
}

__global__ void fill_kernel(const int* __restrict__ tok) {
    int i = blockIdx.x * blockDim.x + threadIdx.x;
    if (i >= NTOK) return;
    int b = i >> 12;
    int base = b * Tn + tok[i];
    int e0 = base % Ee, e1 = (base + 1) % Ee;
    int p0 = atomicAdd(&g_fill[e0], 1); g_rows[g_off[e0] + p0] = i;
    int p1 = atomicAdd(&g_fill[e1], 1); g_rows[g_off[e1] + p1] = i;
}

// ---------------------------------------------------------------------------
// mma.sync tf32 grouped GEMM
// Tile 128x128, BK=32, 256 threads = 8 warps (4 m x 2 n), warp tile 32x64.
// A smem: [128][36]  (row-major, pad 4)   -> fragment reads conflict-free
// B smem: [32][132]  ([k][n], pad 4)      -> weights already [K][N] in gmem!
// G1:  A = x gathered via g_rows,  out = gelu(acc + b1) -> g_h
// !G1: A = g_h (slots),            out += atomicAdd 0.25*(acc + b2)
// ---------------------------------------------------------------------------
#define A_STRIDE 36
#define B_STRIDE 132
#define A_ELEMS  (128 * A_STRIDE)          /* 4608 floats */
#define B_ELEMS  (32 * B_STRIDE)           /* 4224 floats */
#define SMEM_FLOATS (2 * (A_ELEMS + B_ELEMS))
#define SMEM_BYTES  (SMEM_FLOATS * 4)      /* 70656 */

template <bool G1>
__global__ __launch_bounds__(256, 1) void moe_gemm_mma(
    const float* __restrict__ Asrc,     // x (G1) or g_h (!G1)
    const float* __restrict__ Bw,       // W1 (G1) or W2 (!G1): [E][K][N]
    const float* __restrict__ bias,     // b1 or b2
    float* __restrict__ outp)           // g_h (G1) or out (!G1)
{
    constexpr int KTOT  = G1 ? Dm : Ff;      // 512 / 2048
    constexpr int NFULL = G1 ? Ff : Dm;      // 2048 / 512
    constexpr int NC    = KTOT / 32;

    const int e   = blockIdx.z;
    const int cnt = g_cnt[e];
    const int m0  = blockIdx.y * 128;
    if (m0 >= cnt) return;
    const int off = g_off[e];
    const int n0  = blockIdx.x * 128;
    const float* Bsrc = Bw + (size_t)e * KTOT * NFULL;

    extern __shared__ float smem[];
    const uint32_t sb = smem_u32(smem);

    const int t = threadIdx.x;
    const int lane = t & 31, warp = t >> 5;
    const int wm = warp & 3, wn = warp >> 2;
    const int qr = lane >> 2, qc = lane & 3;

    // ---- global load pointers ----
    // A: 4 iterations, each thread: row = it*32 + t>>3, col group = t&7 (float4)
    const float* aptr[4];
#pragma unroll
    for (int it = 0; it < 4; it++) {
        int gi = m0 + it * 32 + (t >> 3);
        if (gi >= cnt) gi = cnt - 1;
        size_t r = G1 ? (size_t)g_rows[off + gi] : (size_t)(off + gi);
        aptr[it] = Asrc + r * KTOT + (t & 7) * 4;
    }
    // B: 4 iterations, each thread: k-row = it*8 + t>>5, col group = t&31 (float4)
    const float* bptr[4];
#pragma unroll
    for (int it = 0; it < 4; it++)
        bptr[it] = Bsrc + (size_t)(it * 8 + (t >> 5)) * NFULL + n0 + (t & 31) * 4;

    // smem dst addresses (constant per thread, per buffer)
    uint32_t adst[2][4], bdst[2][4];
#pragma unroll
    for (int buf = 0; buf < 2; buf++) {
        uint32_t abase = sb + buf * A_ELEMS * 4;
        uint32_t bbase = sb + (2 * A_ELEMS + buf * B_ELEMS) * 4;
#pragma unroll
        for (int it = 0; it < 4; it++) {
            adst[buf][it] = abase + ((it * 32 + (t >> 3)) * A_STRIDE + (t & 7) * 4) * 4;
            bdst[buf][it] = bbase + ((it * 8 + (t >> 5)) * B_STRIDE + (t & 31) * 4) * 4;
        }
    }

    auto load_chunk = [&](int c) {
        int buf = c & 1;
        int k0 = c * 32;
#pragma unroll
        for (int it = 0; it < 4; it++) CP16(adst[buf][it], aptr[it] + k0);
#pragma unroll
        for (int it = 0; it < 4; it++) CP16(bdst[buf][it], bptr[it] + (size_t)k0 * NFULL);
        CP_COMMIT();
    };

    float acc[2][8][4];
#pragma unroll
    for (int fm = 0; fm < 2; fm++)
#pragma unroll
        for (int fn = 0; fn < 8; fn++)
#pragma unroll
            for (int q = 0; q < 4; q++) acc[fm][fn][q] = 0.f;

    load_chunk(0);

    for (int c = 0; c < NC; c++) {
        if (c + 1 < NC) { load_chunk(c + 1); CP_WAIT(1); }
        else           { CP_WAIT(0); }
        __syncthreads();

        const float* A = smem + (c & 1) * A_ELEMS;
        const float* B = smem + 2 * A_ELEMS + (c & 1) * B_ELEMS;

#pragma unroll
        for (int ks = 0; ks < 4; ks++) {
            int k = ks * 8;
            uint32_t a[2][4], b[8][2];
#pragma unroll
            for (int fm = 0; fm < 2; fm++) {
                int r = wm * 32 + fm * 16 + qr;
                a[fm][0] = f2tf32(A[r * A_STRIDE + k + qc]);
                a[fm][1] = f2tf32(A[(r + 8) * A_STRIDE + k + qc]);
                a[fm][2] = f2tf32(A[r * A_STRIDE + k + qc + 4]);
                a[fm][3] = f2tf32(A[(r + 8) * A_STRIDE + k + qc + 4]);
            }
#pragma unroll
            for (int fn = 0; fn < 8; fn++) {
                int col = wn * 64 + fn * 8 + qr;
                b[fn][0] = f2tf32(B[(k + qc) * B_STRIDE + col]);
                b[fn][1] = f2tf32(B[(k + qc + 4) * B_STRIDE + col]);
            }
#pragma unroll
            for (int fm = 0; fm < 2; fm++)
#pragma unroll
                for (int fn = 0; fn < 8; fn++)
                    mma_tf32(acc[fm][fn], a[fm], b[fn]);
        }
        __syncthreads();
    }

    // ---- epilogue ----
    // acc[fm][fn][{0,1}] -> row qr,    cols 2*qc, 2*qc+1
    // acc[fm][fn][{2,3}] -> row qr+8,  cols 2*qc, 2*qc+1
#pragma unroll
    for (int fm = 0; fm < 2; fm++) {
#pragma unroll
        for (int rr = 0; rr < 2; rr++) {
            int m = m0 + wm * 32 + fm * 16 + rr * 8 + qr;
            if (m >= cnt) continue;
            float* orow;
            if (G1) orow = outp + (size_t)(off + m) * Ff;
            else    orow = outp + (size_t)g_rows[off + m] * Dm;
#pragma unroll
            for (int fn = 0; fn < 8; fn++) {
                int col = n0 + wn * 64 + fn * 8 + 2 * qc;
                float v0 = acc[fm][fn][rr * 2 + 0] + bias[e * NFULL + col];
                float v1 = acc[fm][fn][rr * 2 + 1] + bias[e * NFULL + col + 1];
                if (G1) {
                    float2 g;
                    g.x = 0.5f * v0 * (1.0f + erff(v0 * 0.7071067811865476f));
                    g.y = 0.5f * v1 * (1.0f + erff(v1 * 0.7071067811865476f));
                    *(float2*)(orow + col) = g;
                } else {
                    atomicAdd(&orow[col],     0.25f * v0);
                    atomicAdd(&orow[col + 1], 0.25f * v1);
                }
            }
        }
    }
}

// ---------------------------------------------------------------------------
// Launch
// ---------------------------------------------------------------------------
extern "C" void kernel_launch(void* const* d_in, const int* in_sizes, int n_in,
                              void* d_out, int out_size) {
    const float* x   = (const float*)d_in[0];
    const int*   tok = (const int*)d_in[1];
    const float* W1  = (const float*)d_in[2];
    const float* b1  = (const float*)d_in[3];
    const float* W2  = (const float*)d_in[4];
    const float* b2  = (const float*)d_in[5];

    float* out  = (float*)d_out;
    float* eid  = out + (size_t)NTOK * Dm;
    float* ecnt = eid + (size_t)NASG;

    static bool attr_set = false;
    if (!attr_set) {
        cudaFuncSetAttribute(moe_gemm_mma<true>,  cudaFuncAttributeMaxDynamicSharedMemorySize, SMEM_BYTES);
        cudaFuncSetAttribute(moe_gemm_mma<false>, cudaFuncAttributeMaxDynamicSharedMemorySize, SMEM_BYTES);
        attr_set = true;
    }

    float* hbuf; cudaGetSymbolAddress((void**)&hbuf, g_h);

    int n4 = (NTOK * Dm) / 4;
    zero_and_reset<<<4096, 256>>>((float4*)out, n4);
    route_kernel<<<NTOK / 256, 256>>>(tok, eid);
    offsets_kernel<<<1, 32>>>(ecnt);
    fill_kernel<<<NTOK / 256, 256>>>(tok);

    dim3 g1(Ff / 128, 96, Ee);   // 16 n-tiles, up to 96 m-tiles (early exit), 8 experts
    moe_gemm_mma<true><<<g1, 256, SMEM_BYTES>>>(x, W1, b1, hbuf);
    dim3 g2(Dm / 128, 96, Ee);   // 4 n-tiles
    moe_gemm_mma<false><<<g2, 256, SMEM_BYTES>>>(hbuf, W2, b2, out);
}